// round 15
// baseline (speedup 1.0000x reference)
#include <cuda_runtime.h>
#include <cuda_fp16.h>
#include <math.h>
#include <stdint.h>

#define NN 20000
#define EE 320000
#define HH 4
#define QW 1536   // 6*C
#define NP 20096  // 157 * 128 (padded M)

// ---------------- scratch (static device globals) ----------------
__device__ __align__(16) float g_qkv1[NN * QW];   // only q_a / q_b sections written
__device__ __align__(16) float g_qkv2[NN * QW];
// fp16 attention operands, row = [k_a(0) | v_a(256) | k_b(512) | v_b(768)]
__device__ __align__(16) __half g_kv1[NN * 1024];
__device__ __align__(16) __half g_kv2[NN * 1024];
__device__ float g_rpe[16];

// CSR per graph
__device__ int g_deg[4][NN];
__device__ int g_off[4][NN + 1];
__device__ int g_eidx[4][EE];
__device__ int g_srcs[4][EE];

// fp16 GEMM operands
__device__ __align__(16) __half g_f1p[NP * 256];
__device__ __align__(16) __half g_f2p[NP * 256];
__device__ __align__(16) __half g_t1p[NP * 512];
__device__ __align__(16) __half g_t2p[NP * 512];
__device__ __align__(16) __half g_w1p[1536 * 256];
__device__ __align__(16) __half g_w2p[1536 * 256];
__device__ __align__(16) __half g_p1p[256 * 512];
__device__ __align__(16) __half g_p2p[256 * 512];

// ---------------- helpers ----------------
__device__ __forceinline__ uint32_t smem_u32(const void* p) {
    uint32_t a;
    asm("{ .reg .u64 t; cvta.to.shared.u64 t, %1; cvt.u32.u64 %0, t; }" : "=r"(a) : "l"(p));
    return a;
}
__device__ __forceinline__ void cp_async16(uint32_t dst, const void* src) {
    asm volatile("cp.async.cg.shared.global [%0], [%1], 16;" :: "r"(dst), "l"(src));
}
__device__ __forceinline__ void cp_commit() {
    asm volatile("cp.async.commit_group;" ::: "memory");
}
__device__ __forceinline__ void cp_wait0() {
    asm volatile("cp.async.wait_group 0;" ::: "memory");
}
__device__ __forceinline__ void ldmatrix4(uint32_t* r, uint32_t addr) {
    asm volatile("ldmatrix.sync.aligned.m8n8.x4.shared.b16 {%0,%1,%2,%3}, [%4];"
                 : "=r"(r[0]), "=r"(r[1]), "=r"(r[2]), "=r"(r[3]) : "r"(addr));
}
__device__ __forceinline__ void mma16816(float* c, const uint32_t* a, const uint32_t* b) {
    asm volatile("mma.sync.aligned.m16n8k16.row.col.f32.f16.f16.f32 "
                 "{%0,%1,%2,%3}, {%4,%5,%6,%7}, {%8,%9}, {%0,%1,%2,%3};"
                 : "+f"(c[0]), "+f"(c[1]), "+f"(c[2]), "+f"(c[3])
                 : "r"(a[0]), "r"(a[1]), "r"(a[2]), "r"(a[3]), "r"(b[0]), "r"(b[1]));
}

// ---------------- prep: rpe + zero CSR counters + zero t-buffer pad rows ----------------
#define TPADV (((NP - NN) * 512) / 8)
__global__ void prep_all(const float* __restrict__ Wrpe, const float* __restrict__ brpe) {
    int gid = blockIdx.x * blockDim.x + threadIdx.x;
    int stride = gridDim.x * blockDim.x;

    if (blockIdx.x == 0 && threadIdx.x < HH) {
        int h = threadIdx.x;
        for (int p = 0; p < 3; p++) {
            float s = 0.f;
            for (int d = 0; d < 64; d++) s += Wrpe[p * 256 + h * 64 + d];
            g_rpe[p * HH + h] = s;
        }
        float b = 0.f;
        for (int d = 0; d < 64; d++) b += brpe[h * 64 + d];
        g_rpe[12 + h] = b;
    }

    int* d = &g_deg[0][0];
    for (int j = gid; j < 4 * NN; j += stride) d[j] = 0;

    uint4 zz = make_uint4(0, 0, 0, 0);
    uint4* t1 = (uint4*)(&g_t1p[(size_t)NN * 512]);
    uint4* t2 = (uint4*)(&g_t2p[(size_t)NN * 512]);
    for (int j = gid; j < TPADV; j += stride) { t1[j] = zz; t2[j] = zz; }
}

// ---------------- CSR build ----------------
__global__ void count4(const int* __restrict__ g0, const int* __restrict__ g1,
                       const int* __restrict__ g2, const int* __restrict__ g3) {
    int aid = blockIdx.y;
    const int* g = (aid == 0) ? g0 : (aid == 1) ? g1 : (aid == 2) ? g2 : g3;
    int i = blockIdx.x * blockDim.x + threadIdx.x;
    if (i < EE) g_eidx[aid][i] = atomicAdd(&g_deg[aid][g[i]], 1);
}
#define SCAN_SMEM (NN * 4)
__global__ void scan_kernel() {
    extern __shared__ int sd[];
    __shared__ int ssum[1024];
    int aid = blockIdx.x;
    int t = threadIdx.x;

    for (int i = t; i < NN; i += 1024) sd[i] = g_deg[aid][i];
    __syncthreads();

    const int CH = 20;
    int base = t * CH;
    int loc[CH];
    int s = 0;
#pragma unroll
    for (int i = 0; i < CH; i++) {
        int idx = base + i;
        int v = (idx < NN) ? sd[idx] : 0;
        loc[i] = s; s += v;
    }
    ssum[t] = s;
    __syncthreads();
    for (int o = 1; o < 1024; o <<= 1) {
        int v = (t >= o) ? ssum[t - o] : 0;
        __syncthreads();
        ssum[t] += v;
        __syncthreads();
    }
    int offs = (t > 0) ? ssum[t - 1] : 0;
#pragma unroll
    for (int i = 0; i < CH; i++) {
        int idx = base + i;
        if (idx < NN) sd[idx] = offs + loc[i];
    }
    __syncthreads();
    for (int i = t; i < NN; i += 1024) g_off[aid][i] = sd[i];
    if (t == 1023) g_off[aid][NN] = ssum[1023];
}
__global__ void permute4(const int* __restrict__ g0, const int* __restrict__ g1,
                         const int* __restrict__ g2, const int* __restrict__ g3) {
    int aid = blockIdx.y;
    const int* g = (aid == 0) ? g0 : (aid == 1) ? g1 : (aid == 2) ? g2 : g3;
    int i = blockIdx.x * blockDim.x + threadIdx.x;
    if (i >= EE) return;
    int d = g[i];
    int p = g_off[aid][d] + g_eidx[aid][i];
    g_srcs[aid][p] = g[EE + i];
}

// ---------------- feat convert: [NN,256] f32 -> [NP,256] fp16 ----------------
#define FSV (NP * 256 / 8)
__global__ void split_feats(const float* __restrict__ feat1, const float* __restrict__ feat2,
                            __half* __restrict__ d1, __half* __restrict__ d2) {
    const float* src = blockIdx.y ? feat2 : feat1;
    __half* dst = blockIdx.y ? d2 : d1;
    int i8 = blockIdx.x * blockDim.x + threadIdx.x;
    if (i8 >= FSV) return;
    int r = i8 >> 5;
    int kk = (i8 & 31) << 3;
    __align__(16) __half h8[8];
    if (r < NN) {
        float4 x0 = *(const float4*)(src + (size_t)r * 256 + kk);
        float4 x1 = *(const float4*)(src + (size_t)r * 256 + kk + 4);
        h8[0] = __float2half_rn(x0.x); h8[1] = __float2half_rn(x0.y);
        h8[2] = __float2half_rn(x0.z); h8[3] = __float2half_rn(x0.w);
        h8[4] = __float2half_rn(x1.x); h8[5] = __float2half_rn(x1.y);
        h8[6] = __float2half_rn(x1.z); h8[7] = __float2half_rn(x1.w);
    } else {
#pragma unroll
        for (int j = 0; j < 8; j++) h8[j] = __float2half_rn(0.f);
    }
    *(uint4*)(dst + (size_t)r * 256 + kk) = *(const uint4*)h8;
}

// ---------------- coalesced weight transpose: W [K,Nc] f32 -> dst [Nc,K] fp16 ----------------
__global__ void transposeW2c(const float* __restrict__ Wa, const float* __restrict__ Wb,
                             __half* __restrict__ oa, __half* __restrict__ ob,
                             int K, int Nc) {
    const float* W = blockIdx.z ? Wb : Wa;
    __half* dst = blockIdx.z ? ob : oa;
    __shared__ __half tile[32][33];
    int n0 = blockIdx.x * 32, k0 = blockIdx.y * 32;
    int tx = threadIdx.x, ty = threadIdx.y;
#pragma unroll
    for (int i = ty; i < 32; i += 8)
        tile[i][tx] = __float2half_rn(W[(size_t)(k0 + i) * Nc + n0 + tx]);
    __syncthreads();
#pragma unroll
    for (int i = ty; i < 32; i += 8)
        dst[(size_t)(n0 + i) * K + k0 + tx] = tile[tx][i];
}

// ---------------- fused per-node attention (fp16 k/v, fp16 out) ----------------
__global__ __launch_bounds__(256)
void attn4(const float* __restrict__ qkv1, const float* __restrict__ qkv2,
           const __half* __restrict__ kv1, const __half* __restrict__ kv2,
           const float* __restrict__ coord1, const float* __restrict__ coord2,
           __half* __restrict__ t1p, __half* __restrict__ t2p, int aidbase) {
    int aid = aidbase + 2 * blockIdx.y;
    const float* qkvQ;
    const __half* kvSrc;
    const float *coordD, *coordS;
    __half* outp;
    int qoff, koff, voff, outoff, useRpe;
    switch (aid) {
        case 0: qkvQ = qkv1; qoff = 0;   kvSrc = kv1; koff = 0;   voff = 256;
                coordD = coord1; coordS = coord1; useRpe = 1; outp = t1p; outoff = 0;   break;
        case 1: qkvQ = qkv2; qoff = 768; kvSrc = kv2; koff = 512; voff = 768;
                coordD = coord2; coordS = coord2; useRpe = 1; outp = t2p; outoff = 0;   break;
        case 2: qkvQ = qkv1; qoff = 768; kvSrc = kv2; koff = 0;   voff = 256;
                coordD = nullptr; coordS = nullptr; useRpe = 0; outp = t1p; outoff = 256; break;
        default:qkvQ = qkv2; qoff = 0;   kvSrc = kv1; koff = 512; voff = 768;
                coordD = nullptr; coordS = nullptr; useRpe = 0; outp = t2p; outoff = 256; break;
    }

    int w = (blockIdx.x * blockDim.x + threadIdx.x) >> 5;
    if (w >= NN) return;
    int lane = threadIdx.x & 31;
    int h = lane >> 3;
    int dsub = (lane & 7) << 3;

    const float* qrow = qkvQ + (size_t)w * QW + qoff + h * 64 + dsub;
    float4 q0 = *(const float4*)(qrow);
    float4 q1 = *(const float4*)(qrow + 4);

    const __half* kbase = kvSrc + koff + h * 64 + dsub;
    const __half* vbase = kvSrc + voff + h * 64 + dsub;

    float r0 = 0.f, r1 = 0.f, r2 = 0.f, rb = 0.f, c0 = 0.f, c1 = 0.f, c2 = 0.f;
    if (useRpe) {
        r0 = g_rpe[h]; r1 = g_rpe[4 + h]; r2 = g_rpe[8 + h]; rb = g_rpe[12 + h];
        c0 = coordD[w * 3 + 0]; c1 = coordD[w * 3 + 1]; c2 = coordD[w * 3 + 2];
    }

    int s0 = g_off[aid][w], s1 = g_off[aid][w + 1];
    float a0 = 0.f, a1 = 0.f, a2 = 0.f, a3 = 0.f, a4 = 0.f, a5 = 0.f, a6 = 0.f, a7 = 0.f;
    float den = 0.f;

#pragma unroll 4
    for (int p = s0; p < s1; p++) {
        int src = g_srcs[aid][p];
        uint4 kraw = *(const uint4*)(kbase + (size_t)src * 1024);
        uint4 vraw = *(const uint4*)(vbase + (size_t)src * 1024);
        float2 kf0 = __half22float2(*(const __half2*)&kraw.x);
        float2 kf1 = __half22float2(*(const __half2*)&kraw.y);
        float2 kf2 = __half22float2(*(const __half2*)&kraw.z);
        float2 kf3 = __half22float2(*(const __half2*)&kraw.w);
        float dot = q0.x * kf0.x + q0.y * kf0.y + q0.z * kf1.x + q0.w * kf1.y
                  + q1.x * kf2.x + q1.y * kf2.y + q1.z * kf3.x + q1.w * kf3.y;
        dot += __shfl_xor_sync(0xffffffffu, dot, 1);
        dot += __shfl_xor_sync(0xffffffffu, dot, 2);
        dot += __shfl_xor_sync(0xffffffffu, dot, 4);
        if (useRpe) {
            float d0 = c0 - coordS[src * 3 + 0];
            float d1 = c1 - coordS[src * 3 + 1];
            float d2 = c2 - coordS[src * 3 + 2];
            dot += d0 * r0 + d1 * r1 + d2 * r2 + rb;
        }
        float esc = __expf(dot);
        den += esc;
        float2 vf0 = __half22float2(*(const __half2*)&vraw.x);
        float2 vf1 = __half22float2(*(const __half2*)&vraw.y);
        float2 vf2 = __half22float2(*(const __half2*)&vraw.z);
        float2 vf3 = __half22float2(*(const __half2*)&vraw.w);
        a0 += esc * vf0.x; a1 += esc * vf0.y; a2 += esc * vf1.x; a3 += esc * vf1.y;
        a4 += esc * vf2.x; a5 += esc * vf2.y; a6 += esc * vf3.x; a7 += esc * vf3.y;
    }

    float inv = (den > 0.f) ? (1.f / den) : 0.f;
    __align__(16) __half h8[8];
    h8[0] = __float2half_rn(a0 * inv); h8[1] = __float2half_rn(a1 * inv);
    h8[2] = __float2half_rn(a2 * inv); h8[3] = __float2half_rn(a3 * inv);
    h8[4] = __float2half_rn(a4 * inv); h8[5] = __float2half_rn(a5 * inv);
    h8[6] = __float2half_rn(a6 * inv); h8[7] = __float2half_rn(a7 * inv);
    *(uint4*)(outp + (size_t)w * 512 + outoff + h * 64 + dsub) = *(const uint4*)h8;
}

// ---------------- fp16 mma.sync GEMM, 128x256 tile, double-buffered ----------------
// C[M,Nc] = A[Mpad,K] @ B[Nc,K]^T + bias.  K % 64 == 0, Nc % 256 == 0.
// 8 warps in 2(M) x 4(N); warp tile 64x64.  blockIdx.z selects set.
// If KV non-null (QKV pass): 256-col section (== blockIdx.x) 1,2,4,5 -> fp16 KV.
#define GSMEM 98304   // 2 stages x (16KB A + 32KB B)

__global__ __launch_bounds__(256)
void gemm_f16_mma2(const __half* __restrict__ A0, const __half* __restrict__ A1,
                   const __half* __restrict__ B0, const __half* __restrict__ B1,
                   const float* __restrict__ bias0, const float* __restrict__ bias1,
                   float* __restrict__ C0, float* __restrict__ C1,
                   __half* __restrict__ KV0, __half* __restrict__ KV1,
                   int M, int K, int Nc) {
    const int z = blockIdx.z;
    const __half* A = z ? A1 : A0;
    const __half* B = z ? B1 : B0;
    const float* bias = z ? bias1 : bias0;
    float* C = z ? C1 : C0;
    __half* KV = z ? KV1 : KV0;

    extern __shared__ char smem[];
    const uint32_t s_u = smem_u32(smem);   // stage s: A at s*49152, B at +16384

    const int t = threadIdx.x;
    const int wid = t >> 5, lane = t & 31;
    const int wm = wid & 1, wn = wid >> 1;      // 2 x 4 warp grid
    const int m0 = blockIdx.y * 128, n0 = blockIdx.x * 256;

    float acc[4][8][4];
#pragma unroll
    for (int i = 0; i < 4; i++)
#pragma unroll
        for (int j = 0; j < 8; j++)
#pragma unroll
            for (int v = 0; v < 4; v++) acc[i][j][v] = 0.f;

    auto load_tiles = [&](int buf, int kt) {
        int k0 = kt << 6;
        uint32_t sb = s_u + buf * 49152;
        // A: 128 rows x 64 halfs = 1024 x 16B -> 4 per thread
#pragma unroll
        for (int i = 0; i < 4; i++) {
            int lin = i * 256 + t;
            int row = lin >> 3, ku = lin & 7;
            uint32_t b = (uint32_t)(row * 128 + ku * 16);
            b ^= (b >> 3) & 0x70;
            cp_async16(sb + b, A + (size_t)(m0 + row) * K + k0 + ku * 8);
        }
        // B: 256 rows x 64 halfs = 2048 x 16B -> 8 per thread
#pragma unroll
        for (int i = 0; i < 8; i++) {
            int lin = i * 256 + t;
            int row = lin >> 3, ku = lin & 7;
            uint32_t b = (uint32_t)(row * 128 + ku * 16);
            b ^= (b >> 3) & 0x70;
            cp_async16(sb + 16384 + b, B + (size_t)(n0 + row) * K + k0 + ku * 8);
        }
    };

    const int nk = K >> 6;   // 4 (QKV) or 8 (proj)
    load_tiles(0, 0);
    cp_commit();

    int buf = 0;
    for (int kt = 0; kt < nk; kt++) {
        cp_wait0();
        __syncthreads();
        if (kt + 1 < nk) { load_tiles(buf ^ 1, kt + 1); cp_commit(); }

        const uint32_t bufA = s_u + buf * 49152;
        const uint32_t bufB = bufA + 16384;
#pragma unroll
        for (int kk = 0; kk < 4; kk++) {
            uint32_t afrag[4][4], bfrag[8][2];
            const int kseg = kk * 2 + (lane >> 4);
#pragma unroll
            for (int mt = 0; mt < 4; mt++) {
                int row = wm * 64 + mt * 16 + (lane & 15);
                uint32_t b = (uint32_t)(row * 128 + kseg * 16);
                b ^= (b >> 3) & 0x70;
                ldmatrix4(afrag[mt], bufA + b);
            }
#pragma unroll
            for (int nt2 = 0; nt2 < 4; nt2++) {
                int row = wn * 64 + nt2 * 16 + (lane & 7) + ((lane >> 3) & 1) * 8;
                uint32_t b = (uint32_t)(row * 128 + kseg * 16);
                b ^= (b >> 3) & 0x70;
                uint32_t r[4];
                ldmatrix4(r, bufB + b);
                bfrag[nt2 * 2][0]     = r[0]; bfrag[nt2 * 2][1]     = r[2];
                bfrag[nt2 * 2 + 1][0] = r[1]; bfrag[nt2 * 2 + 1][1] = r[3];
            }
#pragma unroll
            for (int mt = 0; mt < 4; mt++)
#pragma unroll
                for (int nt = 0; nt < 8; nt++)
                    mma16816(acc[mt][nt], afrag[mt], bfrag[nt]);
        }
        __syncthreads();
        buf ^= 1;
    }

    const int sec = blockIdx.x;   // BN == 256 == section width
    const bool iskv = (KV != nullptr) && (sec != 0) && (sec != 3);
    const int kvbase = (sec == 1) ? 0 : (sec == 2) ? 256 : (sec == 4) ? 512 : 768;

#pragma unroll
    for (int mt = 0; mt < 4; mt++) {
        int rbase = m0 + wm * 64 + mt * 16 + (lane >> 2);
#pragma unroll
        for (int nt = 0; nt < 8; nt++) {
            int c = n0 + wn * 64 + nt * 8 + (lane & 3) * 2;
            float bx = bias[c], by = bias[c + 1];
            if (iskv) {
                int kvc = kvbase + (c & 255);
                if (rbase < M) {
                    __half2 o = __floats2half2_rn(acc[mt][nt][0] + bx, acc[mt][nt][1] + by);
                    *(__half2*)(KV + (size_t)rbase * 1024 + kvc) = o;
                }
                if (rbase + 8 < M) {
                    __half2 o = __floats2half2_rn(acc[mt][nt][2] + bx, acc[mt][nt][3] + by);
                    *(__half2*)(KV + (size_t)(rbase + 8) * 1024 + kvc) = o;
                }
            } else {
                if (rbase < M) {
                    float2 o = make_float2(acc[mt][nt][0] + bx, acc[mt][nt][1] + by);
                    *(float2*)(C + (size_t)rbase * Nc + c) = o;
                }
                if (rbase + 8 < M) {
                    float2 o = make_float2(acc[mt][nt][2] + bx, acc[mt][nt][3] + by);
                    *(float2*)(C + (size_t)(rbase + 8) * Nc + c) = o;
                }
            }
        }
    }
}

// ---------------- launch ----------------
extern "C" void kernel_launch(void* const* d_in, const int* in_sizes, int n_in,
                              void* d_out, int out_size) {
    const float* feat1  = (const float*)d_in[0];
    const float* coord1 = (const float*)d_in[1];
    const float* feat2  = (const float*)d_in[2];
    const float* coord2 = (const float*)d_in[3];
    const float* Wqkv1  = (const float*)d_in[4];
    const float* bqkv1  = (const float*)d_in[5];
    const float* Wqkv2  = (const float*)d_in[6];
    const float* bqkv2  = (const float*)d_in[7];
    const float* Wproj1 = (const float*)d_in[8];
    const float* bproj1 = (const float*)d_in[9];
    const float* Wproj2 = (const float*)d_in[10];
    const float* bproj2 = (const float*)d_in[11];
    const float* Wrpe   = (const float*)d_in[12];
    const float* brpe   = (const float*)d_in[13];
    const int* graph1   = (const int*)d_in[14];
    const int* graph2   = (const int*)d_in[15];
    const int* graph12  = (const int*)d_in[16];
    const int* graph21  = (const int*)d_in[17];
    float* out = (float*)d_out;

    float *qkv1, *qkv2;
    __half *kv1, *kv2;
    cudaGetSymbolAddress((void**)&qkv1, g_qkv1);
    cudaGetSymbolAddress((void**)&qkv2, g_qkv2);
    cudaGetSymbolAddress((void**)&kv1, g_kv1);
    cudaGetSymbolAddress((void**)&kv2, g_kv2);
    __half *f1p, *f2p, *t1p, *t2p, *w1p, *w2p, *p1p, *p2p;
    cudaGetSymbolAddress((void**)&f1p, g_f1p);
    cudaGetSymbolAddress((void**)&f2p, g_f2p);
    cudaGetSymbolAddress((void**)&t1p, g_t1p);
    cudaGetSymbolAddress((void**)&t2p, g_t2p);
    cudaGetSymbolAddress((void**)&w1p, g_w1p);
    cudaGetSymbolAddress((void**)&w2p, g_w2p);
    cudaGetSymbolAddress((void**)&p1p, g_p1p);
    cudaGetSymbolAddress((void**)&p2p, g_p2p);

    static cudaStream_t s1 = nullptr;
    static cudaEvent_t evFork = nullptr, evCSR = nullptr, evQKV = nullptr, evDone = nullptr;
    static bool inited = false;
    if (!inited) {
        cudaStreamCreateWithFlags(&s1, cudaStreamNonBlocking);
        cudaEventCreateWithFlags(&evFork, cudaEventDisableTiming);
        cudaEventCreateWithFlags(&evCSR, cudaEventDisableTiming);
        cudaEventCreateWithFlags(&evQKV, cudaEventDisableTiming);
        cudaEventCreateWithFlags(&evDone, cudaEventDisableTiming);
        cudaFuncSetAttribute(gemm_f16_mma2, cudaFuncAttributeMaxDynamicSharedMemorySize, GSMEM);
        cudaFuncSetAttribute(scan_kernel, cudaFuncAttributeMaxDynamicSharedMemorySize, SCAN_SMEM);
        inited = true;
    }

    // s0: prep (zeroes counters used by s1's count4)
    prep_all<<<128, 256>>>(Wrpe, brpe);

    // fork s1: CSR build + proj-weight transpose
    cudaEventRecord(evFork, 0);
    cudaStreamWaitEvent(s1, evFork, 0);

    const int EBLK = (EE + 255) / 256;
    dim3 gcnt(EBLK, 4);
    count4<<<gcnt, 256, 0, s1>>>(graph1, graph2, graph21, graph12);
    scan_kernel<<<4, 1024, SCAN_SMEM, s1>>>();
    permute4<<<gcnt, 256, 0, s1>>>(graph1, graph2, graph21, graph12);
    dim3 gtp(256 / 32, 512 / 32, 2);
    transposeW2c<<<gtp, dim3(32, 8), 0, s1>>>(Wproj1, Wproj2, p1p, p2p, 512, 256);
    cudaEventRecord(evCSR, s1);   // CSR + proj weights ready

    // s0: feat convert + qkv weight transpose + QKV GEMMs (both sets)
    dim3 gfs((FSV + 255) / 256, 2);
    split_feats<<<gfs, 256>>>(feat1, feat2, f1p, f2p);
    dim3 gtw(1536 / 32, 256 / 32, 2);
    transposeW2c<<<gtw, dim3(32, 8)>>>(Wqkv1, Wqkv2, w1p, w2p, 256, 1536);

    dim3 gq(QW / 256, NP / 128, 2);
    gemm_f16_mma2<<<gq, 256, GSMEM>>>(f1p, f2p, w1p, w2p, bqkv1, bqkv2, qkv1, qkv2,
                                      kv1, kv2, NN, 256, QW);
    cudaEventRecord(evQKV, 0);

    // chain A on s0: attn aids {0,2} -> t1p, then proj set1
    cudaStreamWaitEvent(0, evCSR, 0);
    dim3 ga((NN * 32 + 255) / 256, 2);
    attn4<<<ga, 256>>>(qkv1, qkv2, kv1, kv2, coord1, coord2, t1p, t2p, 0);
    dim3 gp(1, NP / 128, 1);
    gemm_f16_mma2<<<gp, 256, GSMEM>>>(t1p, t1p, p1p, p1p, bproj1, bproj1,
                                      out, out, nullptr, nullptr, NN, 512, 256);

    // chain B on s1: attn aids {1,3} -> t2p, then proj set2
    cudaStreamWaitEvent(s1, evQKV, 0);
    attn4<<<ga, 256, 0, s1>>>(qkv1, qkv2, kv1, kv2, coord1, coord2, t1p, t2p, 1);
    gemm_f16_mma2<<<gp, 256, GSMEM, s1>>>(t2p, t2p, p2p, p2p, bproj2, bproj2,
                                          out + (size_t)NN * 256, out + (size_t)NN * 256,
                                          nullptr, nullptr, NN, 512, 256);
    cudaEventRecord(evDone, s1);

    // join all forks back into s0 before capture end
    cudaStreamWaitEvent(0, evDone, 0);
}

// round 16
// speedup vs baseline: 1.0007x; 1.0007x over previous
#include <cuda_runtime.h>
#include <cuda_fp16.h>
#include <math.h>
#include <stdint.h>

#define NN 20000
#define EE 320000
#define HH 4
#define QW 1536   // 6*C
#define NP 20096  // 157 * 128 (padded M)

// ---------------- scratch (static device globals) ----------------
__device__ __align__(16) float g_qkv1[NN * QW];   // only q_a / q_b sections written
__device__ __align__(16) float g_qkv2[NN * QW];
// fp16 attention operands, row = [k_a(0) | v_a(256) | k_b(512) | v_b(768)]
__device__ __align__(16) __half g_kv1[NN * 1024];
__device__ __align__(16) __half g_kv2[NN * 1024];
__device__ float g_rpe[16];

// CSR per graph
__device__ int g_deg[4][NN];
__device__ int g_off[4][NN + 1];
__device__ int g_eidx[4][EE];
__device__ int g_srcs[4][EE];

// fp16 GEMM operands
__device__ __align__(16) __half g_f1p[NP * 256];
__device__ __align__(16) __half g_f2p[NP * 256];
__device__ __align__(16) __half g_t1p[NP * 512];
__device__ __align__(16) __half g_t2p[NP * 512];
__device__ __align__(16) __half g_w1p[1536 * 256];
__device__ __align__(16) __half g_w2p[1536 * 256];
__device__ __align__(16) __half g_p1p[256 * 512];
__device__ __align__(16) __half g_p2p[256 * 512];

// ---------------- helpers ----------------
__device__ __forceinline__ uint32_t smem_u32(const void* p) {
    uint32_t a;
    asm("{ .reg .u64 t; cvta.to.shared.u64 t, %1; cvt.u32.u64 %0, t; }" : "=r"(a) : "l"(p));
    return a;
}
__device__ __forceinline__ void cp_async16(uint32_t dst, const void* src) {
    asm volatile("cp.async.cg.shared.global [%0], [%1], 16;" :: "r"(dst), "l"(src));
}
__device__ __forceinline__ void cp_commit() {
    asm volatile("cp.async.commit_group;" ::: "memory");
}
__device__ __forceinline__ void cp_wait0() {
    asm volatile("cp.async.wait_group 0;" ::: "memory");
}
__device__ __forceinline__ void ldmatrix4(uint32_t* r, uint32_t addr) {
    asm volatile("ldmatrix.sync.aligned.m8n8.x4.shared.b16 {%0,%1,%2,%3}, [%4];"
                 : "=r"(r[0]), "=r"(r[1]), "=r"(r[2]), "=r"(r[3]) : "r"(addr));
}
__device__ __forceinline__ void mma16816(float* c, const uint32_t* a, const uint32_t* b) {
    asm volatile("mma.sync.aligned.m16n8k16.row.col.f32.f16.f16.f32 "
                 "{%0,%1,%2,%3}, {%4,%5,%6,%7}, {%8,%9}, {%0,%1,%2,%3};"
                 : "+f"(c[0]), "+f"(c[1]), "+f"(c[2]), "+f"(c[3])
                 : "r"(a[0]), "r"(a[1]), "r"(a[2]), "r"(a[3]), "r"(b[0]), "r"(b[1]));
}

// ---------------- prep: rpe + zero CSR counters + zero t-buffer pad rows ----------------
#define TPADV (((NP - NN) * 512) / 8)
__global__ void prep_all(const float* __restrict__ Wrpe, const float* __restrict__ brpe) {
    int gid = blockIdx.x * blockDim.x + threadIdx.x;
    int stride = gridDim.x * blockDim.x;

    if (blockIdx.x == 0 && threadIdx.x < HH) {
        int h = threadIdx.x;
        for (int p = 0; p < 3; p++) {
            float s = 0.f;
            for (int d = 0; d < 64; d++) s += Wrpe[p * 256 + h * 64 + d];
            g_rpe[p * HH + h] = s;
        }
        float b = 0.f;
        for (int d = 0; d < 64; d++) b += brpe[h * 64 + d];
        g_rpe[12 + h] = b;
    }

    int* d = &g_deg[0][0];
    for (int j = gid; j < 4 * NN; j += stride) d[j] = 0;

    uint4 zz = make_uint4(0, 0, 0, 0);
    uint4* t1 = (uint4*)(&g_t1p[(size_t)NN * 512]);
    uint4* t2 = (uint4*)(&g_t2p[(size_t)NN * 512]);
    for (int j = gid; j < TPADV; j += stride) { t1[j] = zz; t2[j] = zz; }
}

// ---------------- CSR build ----------------
__global__ void count4(const int* __restrict__ g0, const int* __restrict__ g1,
                       const int* __restrict__ g2, const int* __restrict__ g3) {
    int aid = blockIdx.y;
    const int* g = (aid == 0) ? g0 : (aid == 1) ? g1 : (aid == 2) ? g2 : g3;
    int i = blockIdx.x * blockDim.x + threadIdx.x;
    if (i < EE) g_eidx[aid][i] = atomicAdd(&g_deg[aid][g[i]], 1);
}
#define SCAN_SMEM (NN * 4)
__global__ void scan_kernel() {
    extern __shared__ int sd[];
    __shared__ int ssum[1024];
    int aid = blockIdx.x;
    int t = threadIdx.x;

    for (int i = t; i < NN; i += 1024) sd[i] = g_deg[aid][i];
    __syncthreads();

    const int CH = 20;
    int base = t * CH;
    int loc[CH];
    int s = 0;
#pragma unroll
    for (int i = 0; i < CH; i++) {
        int idx = base + i;
        int v = (idx < NN) ? sd[idx] : 0;
        loc[i] = s; s += v;
    }
    ssum[t] = s;
    __syncthreads();
    for (int o = 1; o < 1024; o <<= 1) {
        int v = (t >= o) ? ssum[t - o] : 0;
        __syncthreads();
        ssum[t] += v;
        __syncthreads();
    }
    int offs = (t > 0) ? ssum[t - 1] : 0;
#pragma unroll
    for (int i = 0; i < CH; i++) {
        int idx = base + i;
        if (idx < NN) sd[idx] = offs + loc[i];
    }
    __syncthreads();
    for (int i = t; i < NN; i += 1024) g_off[aid][i] = sd[i];
    if (t == 1023) g_off[aid][NN] = ssum[1023];
}
__global__ void permute4(const int* __restrict__ g0, const int* __restrict__ g1,
                         const int* __restrict__ g2, const int* __restrict__ g3) {
    int aid = blockIdx.y;
    const int* g = (aid == 0) ? g0 : (aid == 1) ? g1 : (aid == 2) ? g2 : g3;
    int i = blockIdx.x * blockDim.x + threadIdx.x;
    if (i >= EE) return;
    int d = g[i];
    int p = g_off[aid][d] + g_eidx[aid][i];
    g_srcs[aid][p] = g[EE + i];
}

// ---------------- feat convert: [NN,256] f32 -> [NP,256] fp16 ----------------
#define FSV (NP * 256 / 8)
__global__ void split_feats(const float* __restrict__ feat1, const float* __restrict__ feat2,
                            __half* __restrict__ d1, __half* __restrict__ d2) {
    const float* src = blockIdx.y ? feat2 : feat1;
    __half* dst = blockIdx.y ? d2 : d1;
    int i8 = blockIdx.x * blockDim.x + threadIdx.x;
    if (i8 >= FSV) return;
    int r = i8 >> 5;
    int kk = (i8 & 31) << 3;
    __align__(16) __half h8[8];
    if (r < NN) {
        float4 x0 = *(const float4*)(src + (size_t)r * 256 + kk);
        float4 x1 = *(const float4*)(src + (size_t)r * 256 + kk + 4);
        h8[0] = __float2half_rn(x0.x); h8[1] = __float2half_rn(x0.y);
        h8[2] = __float2half_rn(x0.z); h8[3] = __float2half_rn(x0.w);
        h8[4] = __float2half_rn(x1.x); h8[5] = __float2half_rn(x1.y);
        h8[6] = __float2half_rn(x1.z); h8[7] = __float2half_rn(x1.w);
    } else {
#pragma unroll
        for (int j = 0; j < 8; j++) h8[j] = __float2half_rn(0.f);
    }
    *(uint4*)(dst + (size_t)r * 256 + kk) = *(const uint4*)h8;
}

// ---------------- coalesced weight transpose: W [K,Nc] f32 -> dst [Nc,K] fp16 ----------------
__global__ void transposeW2c(const float* __restrict__ Wa, const float* __restrict__ Wb,
                             __half* __restrict__ oa, __half* __restrict__ ob,
                             int K, int Nc) {
    const float* W = blockIdx.z ? Wb : Wa;
    __half* dst = blockIdx.z ? ob : oa;
    __shared__ __half tile[32][33];
    int n0 = blockIdx.x * 32, k0 = blockIdx.y * 32;
    int tx = threadIdx.x, ty = threadIdx.y;
#pragma unroll
    for (int i = ty; i < 32; i += 8)
        tile[i][tx] = __float2half_rn(W[(size_t)(k0 + i) * Nc + n0 + tx]);
    __syncthreads();
#pragma unroll
    for (int i = ty; i < 32; i += 8)
        dst[(size_t)(n0 + i) * K + k0 + tx] = tile[tx][i];
}

// ---------------- fused per-node attention (fp16 k/v, fp16 out) ----------------
__global__ __launch_bounds__(256)
void attn4(const float* __restrict__ qkv1, const float* __restrict__ qkv2,
           const __half* __restrict__ kv1, const __half* __restrict__ kv2,
           const float* __restrict__ coord1, const float* __restrict__ coord2,
           __half* __restrict__ t1p, __half* __restrict__ t2p, int aidbase) {
    int aid = aidbase + 2 * blockIdx.y;
    const float* qkvQ;
    const __half* kvSrc;
    const float *coordD, *coordS;
    __half* outp;
    int qoff, koff, voff, outoff, useRpe;
    switch (aid) {
        case 0: qkvQ = qkv1; qoff = 0;   kvSrc = kv1; koff = 0;   voff = 256;
                coordD = coord1; coordS = coord1; useRpe = 1; outp = t1p; outoff = 0;   break;
        case 1: qkvQ = qkv2; qoff = 768; kvSrc = kv2; koff = 512; voff = 768;
                coordD = coord2; coordS = coord2; useRpe = 1; outp = t2p; outoff = 0;   break;
        case 2: qkvQ = qkv1; qoff = 768; kvSrc = kv2; koff = 0;   voff = 256;
                coordD = nullptr; coordS = nullptr; useRpe = 0; outp = t1p; outoff = 256; break;
        default:qkvQ = qkv2; qoff = 0;   kvSrc = kv1; koff = 512; voff = 768;
                coordD = nullptr; coordS = nullptr; useRpe = 0; outp = t2p; outoff = 256; break;
    }

    int w = (blockIdx.x * blockDim.x + threadIdx.x) >> 5;
    if (w >= NN) return;
    int lane = threadIdx.x & 31;
    int h = lane >> 3;
    int dsub = (lane & 7) << 3;

    const float* qrow = qkvQ + (size_t)w * QW + qoff + h * 64 + dsub;
    float4 q0 = *(const float4*)(qrow);
    float4 q1 = *(const float4*)(qrow + 4);

    const __half* kbase = kvSrc + koff + h * 64 + dsub;
    const __half* vbase = kvSrc + voff + h * 64 + dsub;

    float r0 = 0.f, r1 = 0.f, r2 = 0.f, rb = 0.f, c0 = 0.f, c1 = 0.f, c2 = 0.f;
    if (useRpe) {
        r0 = g_rpe[h]; r1 = g_rpe[4 + h]; r2 = g_rpe[8 + h]; rb = g_rpe[12 + h];
        c0 = coordD[w * 3 + 0]; c1 = coordD[w * 3 + 1]; c2 = coordD[w * 3 + 2];
    }

    int s0 = g_off[aid][w], s1 = g_off[aid][w + 1];
    float a0 = 0.f, a1 = 0.f, a2 = 0.f, a3 = 0.f, a4 = 0.f, a5 = 0.f, a6 = 0.f, a7 = 0.f;
    float den = 0.f;

#pragma unroll 4
    for (int p = s0; p < s1; p++) {
        int src = g_srcs[aid][p];
        uint4 kraw = *(const uint4*)(kbase + (size_t)src * 1024);
        uint4 vraw = *(const uint4*)(vbase + (size_t)src * 1024);
        float2 kf0 = __half22float2(*(const __half2*)&kraw.x);
        float2 kf1 = __half22float2(*(const __half2*)&kraw.y);
        float2 kf2 = __half22float2(*(const __half2*)&kraw.z);
        float2 kf3 = __half22float2(*(const __half2*)&kraw.w);
        float dot = q0.x * kf0.x + q0.y * kf0.y + q0.z * kf1.x + q0.w * kf1.y
                  + q1.x * kf2.x + q1.y * kf2.y + q1.z * kf3.x + q1.w * kf3.y;
        dot += __shfl_xor_sync(0xffffffffu, dot, 1);
        dot += __shfl_xor_sync(0xffffffffu, dot, 2);
        dot += __shfl_xor_sync(0xffffffffu, dot, 4);
        if (useRpe) {
            float d0 = c0 - coordS[src * 3 + 0];
            float d1 = c1 - coordS[src * 3 + 1];
            float d2 = c2 - coordS[src * 3 + 2];
            dot += d0 * r0 + d1 * r1 + d2 * r2 + rb;
        }
        float esc = __expf(dot);
        den += esc;
        float2 vf0 = __half22float2(*(const __half2*)&vraw.x);
        float2 vf1 = __half22float2(*(const __half2*)&vraw.y);
        float2 vf2 = __half22float2(*(const __half2*)&vraw.z);
        float2 vf3 = __half22float2(*(const __half2*)&vraw.w);
        a0 += esc * vf0.x; a1 += esc * vf0.y; a2 += esc * vf1.x; a3 += esc * vf1.y;
        a4 += esc * vf2.x; a5 += esc * vf2.y; a6 += esc * vf3.x; a7 += esc * vf3.y;
    }

    float inv = (den > 0.f) ? (1.f / den) : 0.f;
    __align__(16) __half h8[8];
    h8[0] = __float2half_rn(a0 * inv); h8[1] = __float2half_rn(a1 * inv);
    h8[2] = __float2half_rn(a2 * inv); h8[3] = __float2half_rn(a3 * inv);
    h8[4] = __float2half_rn(a4 * inv); h8[5] = __float2half_rn(a5 * inv);
    h8[6] = __float2half_rn(a6 * inv); h8[7] = __float2half_rn(a7 * inv);
    *(uint4*)(outp + (size_t)w * 512 + outoff + h * 64 + dsub) = *(const uint4*)h8;
}

// ---------------- fp16 mma.sync GEMM, 128x256 tile, double-buffered ----------------
// C[M,Nc] = A[Mpad,K] @ B[Nc,K]^T + bias.  K % 64 == 0, Nc % 256 == 0.
// 8 warps in 2(M) x 4(N); warp tile 64x64.  blockIdx.z selects set.
// If KV non-null (QKV pass): 256-col section (== blockIdx.x) 1,2,4,5 -> fp16 KV.
#define GSMEM 98304   // 2 stages x (16KB A + 32KB B)

__global__ __launch_bounds__(256)
void gemm_f16_mma2(const __half* __restrict__ A0, const __half* __restrict__ A1,
                   const __half* __restrict__ B0, const __half* __restrict__ B1,
                   const float* __restrict__ bias0, const float* __restrict__ bias1,
                   float* __restrict__ C0, float* __restrict__ C1,
                   __half* __restrict__ KV0, __half* __restrict__ KV1,
                   int M, int K, int Nc) {
    const int z = blockIdx.z;
    const __half* A = z ? A1 : A0;
    const __half* B = z ? B1 : B0;
    const float* bias = z ? bias1 : bias0;
    float* C = z ? C1 : C0;
    __half* KV = z ? KV1 : KV0;

    extern __shared__ char smem[];
    const uint32_t s_u = smem_u32(smem);   // stage s: A at s*49152, B at +16384

    const int t = threadIdx.x;
    const int wid = t >> 5, lane = t & 31;
    const int wm = wid & 1, wn = wid >> 1;      // 2 x 4 warp grid
    const int m0 = blockIdx.y * 128, n0 = blockIdx.x * 256;

    float acc[4][8][4];
#pragma unroll
    for (int i = 0; i < 4; i++)
#pragma unroll
        for (int j = 0; j < 8; j++)
#pragma unroll
            for (int v = 0; v < 4; v++) acc[i][j][v] = 0.f;

    auto load_tiles = [&](int buf, int kt) {
        int k0 = kt << 6;
        uint32_t sb = s_u + buf * 49152;
        // A: 128 rows x 64 halfs = 1024 x 16B -> 4 per thread
#pragma unroll
        for (int i = 0; i < 4; i++) {
            int lin = i * 256 + t;
            int row = lin >> 3, ku = lin & 7;
            uint32_t b = (uint32_t)(row * 128 + ku * 16);
            b ^= (b >> 3) & 0x70;
            cp_async16(sb + b, A + (size_t)(m0 + row) * K + k0 + ku * 8);
        }
        // B: 256 rows x 64 halfs = 2048 x 16B -> 8 per thread
#pragma unroll
        for (int i = 0; i < 8; i++) {
            int lin = i * 256 + t;
            int row = lin >> 3, ku = lin & 7;
            uint32_t b = (uint32_t)(row * 128 + ku * 16);
            b ^= (b >> 3) & 0x70;
            cp_async16(sb + 16384 + b, B + (size_t)(n0 + row) * K + k0 + ku * 8);
        }
    };

    const int nk = K >> 6;   // 4 (QKV) or 8 (proj)
    load_tiles(0, 0);
    cp_commit();

    int buf = 0;
    for (int kt = 0; kt < nk; kt++) {
        cp_wait0();
        __syncthreads();
        if (kt + 1 < nk) { load_tiles(buf ^ 1, kt + 1); cp_commit(); }

        const uint32_t bufA = s_u + buf * 49152;
        const uint32_t bufB = bufA + 16384;
#pragma unroll
        for (int kk = 0; kk < 4; kk++) {
            uint32_t afrag[4][4], bfrag[8][2];
            const int kseg = kk * 2 + (lane >> 4);
#pragma unroll
            for (int mt = 0; mt < 4; mt++) {
                int row = wm * 64 + mt * 16 + (lane & 15);
                uint32_t b = (uint32_t)(row * 128 + kseg * 16);
                b ^= (b >> 3) & 0x70;
                ldmatrix4(afrag[mt], bufA + b);
            }
#pragma unroll
            for (int nt2 = 0; nt2 < 4; nt2++) {
                int row = wn * 64 + nt2 * 16 + (lane & 7) + ((lane >> 3) & 1) * 8;
                uint32_t b = (uint32_t)(row * 128 + kseg * 16);
                b ^= (b >> 3) & 0x70;
                uint32_t r[4];
                ldmatrix4(r, bufB + b);
                bfrag[nt2 * 2][0]     = r[0]; bfrag[nt2 * 2][1]     = r[2];
                bfrag[nt2 * 2 + 1][0] = r[1]; bfrag[nt2 * 2 + 1][1] = r[3];
            }
#pragma unroll
            for (int mt = 0; mt < 4; mt++)
#pragma unroll
                for (int nt = 0; nt < 8; nt++)
                    mma16816(acc[mt][nt], afrag[mt], bfrag[nt]);
        }
        __syncthreads();
        buf ^= 1;
    }

    const int sec = blockIdx.x;   // BN == 256 == section width
    const bool iskv = (KV != nullptr) && (sec != 0) && (sec != 3);
    const int kvbase = (sec == 1) ? 0 : (sec == 2) ? 256 : (sec == 4) ? 512 : 768;

#pragma unroll
    for (int mt = 0; mt < 4; mt++) {
        int rbase = m0 + wm * 64 + mt * 16 + (lane >> 2);
#pragma unroll
        for (int nt = 0; nt < 8; nt++) {
            int c = n0 + wn * 64 + nt * 8 + (lane & 3) * 2;
            float bx = bias[c], by = bias[c + 1];
            if (iskv) {
                int kvc = kvbase + (c & 255);
                if (rbase < M) {
                    __half2 o = __floats2half2_rn(acc[mt][nt][0] + bx, acc[mt][nt][1] + by);
                    *(__half2*)(KV + (size_t)rbase * 1024 + kvc) = o;
                }
                if (rbase + 8 < M) {
                    __half2 o = __floats2half2_rn(acc[mt][nt][2] + bx, acc[mt][nt][3] + by);
                    *(__half2*)(KV + (size_t)(rbase + 8) * 1024 + kvc) = o;
                }
            } else {
                if (rbase < M) {
                    float2 o = make_float2(acc[mt][nt][0] + bx, acc[mt][nt][1] + by);
                    *(float2*)(C + (size_t)rbase * Nc + c) = o;
                }
                if (rbase + 8 < M) {
                    float2 o = make_float2(acc[mt][nt][2] + bx, acc[mt][nt][3] + by);
                    *(float2*)(C + (size_t)(rbase + 8) * Nc + c) = o;
                }
            }
        }
    }
}

// ---------------- launch ----------------
extern "C" void kernel_launch(void* const* d_in, const int* in_sizes, int n_in,
                              void* d_out, int out_size) {
    const float* feat1  = (const float*)d_in[0];
    const float* coord1 = (const float*)d_in[1];
    const float* feat2  = (const float*)d_in[2];
    const float* coord2 = (const float*)d_in[3];
    const float* Wqkv1  = (const float*)d_in[4];
    const float* bqkv1  = (const float*)d_in[5];
    const float* Wqkv2  = (const float*)d_in[6];
    const float* bqkv2  = (const float*)d_in[7];
    const float* Wproj1 = (const float*)d_in[8];
    const float* bproj1 = (const float*)d_in[9];
    const float* Wproj2 = (const float*)d_in[10];
    const float* bproj2 = (const float*)d_in[11];
    const float* Wrpe   = (const float*)d_in[12];
    const float* brpe   = (const float*)d_in[13];
    const int* graph1   = (const int*)d_in[14];
    const int* graph2   = (const int*)d_in[15];
    const int* graph12  = (const int*)d_in[16];
    const int* graph21  = (const int*)d_in[17];
    float* out = (float*)d_out;

    float *qkv1, *qkv2;
    __half *kv1, *kv2;
    cudaGetSymbolAddress((void**)&qkv1, g_qkv1);
    cudaGetSymbolAddress((void**)&qkv2, g_qkv2);
    cudaGetSymbolAddress((void**)&kv1, g_kv1);
    cudaGetSymbolAddress((void**)&kv2, g_kv2);
    __half *f1p, *f2p, *t1p, *t2p, *w1p, *w2p, *p1p, *p2p;
    cudaGetSymbolAddress((void**)&f1p, g_f1p);
    cudaGetSymbolAddress((void**)&f2p, g_f2p);
    cudaGetSymbolAddress((void**)&t1p, g_t1p);
    cudaGetSymbolAddress((void**)&t2p, g_t2p);
    cudaGetSymbolAddress((void**)&w1p, g_w1p);
    cudaGetSymbolAddress((void**)&w2p, g_w2p);
    cudaGetSymbolAddress((void**)&p1p, g_p1p);
    cudaGetSymbolAddress((void**)&p2p, g_p2p);

    static cudaStream_t s1 = nullptr;
    static cudaEvent_t evFork = nullptr, evCSR = nullptr, evQKV = nullptr, evDone = nullptr;
    static bool inited = false;
    if (!inited) {
        cudaStreamCreateWithFlags(&s1, cudaStreamNonBlocking);
        cudaEventCreateWithFlags(&evFork, cudaEventDisableTiming);
        cudaEventCreateWithFlags(&evCSR, cudaEventDisableTiming);
        cudaEventCreateWithFlags(&evQKV, cudaEventDisableTiming);
        cudaEventCreateWithFlags(&evDone, cudaEventDisableTiming);
        cudaFuncSetAttribute(gemm_f16_mma2, cudaFuncAttributeMaxDynamicSharedMemorySize, GSMEM);
        cudaFuncSetAttribute(scan_kernel, cudaFuncAttributeMaxDynamicSharedMemorySize, SCAN_SMEM);
        inited = true;
    }

    // s0: prep (zeroes counters used by s1's count4)
    prep_all<<<128, 256>>>(Wrpe, brpe);

    // fork s1: CSR build + proj-weight transpose
    cudaEventRecord(evFork, 0);
    cudaStreamWaitEvent(s1, evFork, 0);

    const int EBLK = (EE + 255) / 256;
    dim3 gcnt(EBLK, 4);
    count4<<<gcnt, 256, 0, s1>>>(graph1, graph2, graph21, graph12);
    scan_kernel<<<4, 1024, SCAN_SMEM, s1>>>();
    permute4<<<gcnt, 256, 0, s1>>>(graph1, graph2, graph21, graph12);
    dim3 gtp(256 / 32, 512 / 32, 2);
    transposeW2c<<<gtp, dim3(32, 8), 0, s1>>>(Wproj1, Wproj2, p1p, p2p, 512, 256);
    cudaEventRecord(evCSR, s1);   // CSR + proj weights ready

    // s0: feat convert + qkv weight transpose + QKV GEMMs (both sets)
    dim3 gfs((FSV + 255) / 256, 2);
    split_feats<<<gfs, 256>>>(feat1, feat2, f1p, f2p);
    dim3 gtw(1536 / 32, 256 / 32, 2);
    transposeW2c<<<gtw, dim3(32, 8)>>>(Wqkv1, Wqkv2, w1p, w2p, 256, 1536);

    dim3 gq(QW / 256, NP / 128, 2);
    gemm_f16_mma2<<<gq, 256, GSMEM>>>(f1p, f2p, w1p, w2p, bqkv1, bqkv2, qkv1, qkv2,
                                      kv1, kv2, NN, 256, QW);
    cudaEventRecord(evQKV, 0);

    // chain A on s0: attn aids {0,2} -> t1p, then proj set1
    cudaStreamWaitEvent(0, evCSR, 0);
    dim3 ga((NN * 32 + 255) / 256, 2);
    attn4<<<ga, 256>>>(qkv1, qkv2, kv1, kv2, coord1, coord2, t1p, t2p, 0);
    dim3 gp(1, NP / 128, 1);
    gemm_f16_mma2<<<gp, 256, GSMEM>>>(t1p, t1p, p1p, p1p, bproj1, bproj1,
                                      out, out, nullptr, nullptr, NN, 512, 256);

    // chain B on s1: attn aids {1,3} -> t2p, then proj set2
    cudaStreamWaitEvent(s1, evQKV, 0);
    attn4<<<ga, 256, 0, s1>>>(qkv1, qkv2, kv1, kv2, coord1, coord2, t1p, t2p, 1);
    gemm_f16_mma2<<<gp, 256, GSMEM, s1>>>(t2p, t2p, p2p, p2p, bproj2, bproj2,
                                          out + (size_t)NN * 256, out + (size_t)NN * 256,
                                          nullptr, nullptr, NN, 512, 256);
    cudaEventRecord(evDone, s1);

    // join all forks back into s0 before capture end
    cudaStreamWaitEvent(0, evDone, 0);
}